// round 4
// baseline (speedup 1.0000x reference)
#include <cuda_runtime.h>
#include <cuda_bf16.h>
#include <math.h>

#define TT  2048   // tokens
#define DD  1024   // model dim
#define HH  512    // routed expert hidden
#define HSS 1024   // shared expert hidden
#define EE  8      // experts

// ---------------- scratch (device globals; no allocation allowed) -----------
__device__ int   g_cnt[EE];
__device__ int   g_tok[EE * TT];
__device__ float g_wt [EE * TT];
__device__ float g_hid[(size_t)EE * TT * HH];   // routed GLU hidden, 33.5 MB
__device__ float g_hs [(size_t)TT * HSS];       // shared GLU hidden,  8.4 MB

// ---------------- init: zero expert counts ----------------------------------
__global__ void init_kernel() {
    if (threadIdx.x < EE) g_cnt[threadIdx.x] = 0;
}

// ---------------- router: sigmoid gate, top-2, normalize, bucket ------------
__global__ void router_kernel(const float* __restrict__ x,
                              const float* __restrict__ gw) {
    int warp = (blockIdx.x * blockDim.x + threadIdx.x) >> 5;
    int lane = threadIdx.x & 31;
    if (warp >= TT) return;
    const float* xr = x + (size_t)warp * DD;
    float acc[EE];
    #pragma unroll
    for (int e = 0; e < EE; e++) acc[e] = 0.f;
    for (int d = lane; d < DD; d += 32) {
        float xv = xr[d];
        const float* g = gw + (size_t)d * EE;
        #pragma unroll
        for (int e = 0; e < EE; e++) acc[e] += xv * g[e];
    }
    #pragma unroll
    for (int e = 0; e < EE; e++) {
        #pragma unroll
        for (int o = 16; o > 0; o >>= 1)
            acc[e] += __shfl_xor_sync(0xFFFFFFFFu, acc[e], o);
    }
    if (lane == 0) {
        float s[EE];
        #pragma unroll
        for (int e = 0; e < EE; e++) s[e] = 1.f / (1.f + expf(-acc[e]));
        int i0 = 0;
        #pragma unroll
        for (int e = 1; e < EE; e++) if (s[e] > s[i0]) i0 = e;
        int i1 = (i0 == 0) ? 1 : 0;
        #pragma unroll
        for (int e = 0; e < EE; e++) {
            if (e == i0) continue;
            if (s[e] > s[i1]) i1 = e;
        }
        float sum = s[i0] + s[i1];
        float w0 = s[i0] / sum, w1 = s[i1] / sum;
        int p0 = atomicAdd(&g_cnt[i0], 1);
        g_tok[i0 * TT + p0] = warp; g_wt[i0 * TT + p0] = w0;
        int p1 = atomicAdd(&g_cnt[i1], 1);
        g_tok[i1 * TT + p1] = warp; g_wt[i1 * TT + p1] = w1;
    }
}

__device__ __forceinline__ float silu(float v) {
    return v * (1.f / (1.f + expf(-v)));
}

// ---------------- fused GLU GEMM: C = silu(A@B1) * (A@B3) -------------------
// BM=128, BN=64, BK=16; 256 threads; thread tile 8x4 (dual accumulators).
// GATHER=false: A=x direct, writes g_hs  (N=HSS, K=DD)
// GATHER=true:  A=x rows via g_tok[e],   writes g_hid[e] (N=HH, K=DD), e=blockIdx.z
template<bool GATHER>
__global__ __launch_bounds__(256, 2)
void gemm_glu_kernel(const float* __restrict__ A,
                     const float* __restrict__ B1all,
                     const float* __restrict__ B3all,
                     int N, int Kd) {
    int e = GATHER ? blockIdx.z : 0;
    int M;
    const int* tok = nullptr;
    const float* B1 = B1all;
    const float* B3 = B3all;
    float* C;
    if (GATHER) {
        M = g_cnt[e];
        tok = g_tok + e * TT;
        B1 = B1all + (size_t)e * Kd * N;
        B3 = B3all + (size_t)e * Kd * N;
        C  = g_hid + (size_t)e * TT * N;
    } else {
        M = TT;
        C = g_hs;
    }

    int m0 = blockIdx.y * 128;
    int n0 = blockIdx.x * 64;
    if (m0 >= M) return;

    __shared__ float As [16][128];
    __shared__ float Bs1[16][64];
    __shared__ float Bs3[16][64];

    int tid = threadIdx.x;
    int tx = tid & 15;    // n
    int ty = tid >> 4;    // m

    float acc1[8][4], acc3[8][4];
    #pragma unroll
    for (int i = 0; i < 8; i++)
        #pragma unroll
        for (int j = 0; j < 4; j++) { acc1[i][j] = 0.f; acc3[i][j] = 0.f; }

    // A tile: 128x16 = 512 float4; thread loads f=tid and f+256
    int am0 = tid >> 2;          // 0..63
    int am1 = am0 + 64;
    int ak  = (tid & 3) * 4;
    int r0 = m0 + am0, r1 = m0 + am1;
    bool v0 = r0 < M, v1 = r1 < M;
    int t0, t1;
    if (GATHER) { t0 = v0 ? tok[r0] : 0; t1 = v1 ? tok[r1] : 0; }
    else        { t0 = v0 ? r0 : 0;      t1 = v1 ? r1 : 0; }
    const float* arow0 = A + (size_t)t0 * Kd;
    const float* arow1 = A + (size_t)t1 * Kd;

    // B tile: 16x64 = 256 float4
    int bk = tid >> 4;            // 0..15
    int bn = (tid & 15) * 4;

    for (int k0 = 0; k0 < Kd; k0 += 16) {
        float4 a0 = v0 ? *(const float4*)(arow0 + k0 + ak) : make_float4(0, 0, 0, 0);
        float4 a1 = v1 ? *(const float4*)(arow1 + k0 + ak) : make_float4(0, 0, 0, 0);
        As[ak + 0][am0] = a0.x; As[ak + 1][am0] = a0.y;
        As[ak + 2][am0] = a0.z; As[ak + 3][am0] = a0.w;
        As[ak + 0][am1] = a1.x; As[ak + 1][am1] = a1.y;
        As[ak + 2][am1] = a1.z; As[ak + 3][am1] = a1.w;
        *(float4*)&Bs1[bk][bn] = *(const float4*)(B1 + (size_t)(k0 + bk) * N + n0 + bn);
        *(float4*)&Bs3[bk][bn] = *(const float4*)(B3 + (size_t)(k0 + bk) * N + n0 + bn);
        __syncthreads();
        #pragma unroll
        for (int k = 0; k < 16; k++) {
            float4 aA = *(const float4*)&As[k][ty * 8];
            float4 aB = *(const float4*)&As[k][ty * 8 + 4];
            float4 b1 = *(const float4*)&Bs1[k][tx * 4];
            float4 b3 = *(const float4*)&Bs3[k][tx * 4];
            float a[8] = {aA.x, aA.y, aA.z, aA.w, aB.x, aB.y, aB.z, aB.w};
            float f1[4] = {b1.x, b1.y, b1.z, b1.w};
            float f3[4] = {b3.x, b3.y, b3.z, b3.w};
            #pragma unroll
            for (int i = 0; i < 8; i++)
                #pragma unroll
                for (int j = 0; j < 4; j++) {
                    acc1[i][j] += a[i] * f1[j];
                    acc3[i][j] += a[i] * f3[j];
                }
        }
        __syncthreads();
    }

    #pragma unroll
    for (int i = 0; i < 8; i++) {
        int m = m0 + ty * 8 + i;
        if (m >= M) continue;
        float* crow = C + (size_t)m * N + n0 + tx * 4;
        #pragma unroll
        for (int j = 0; j < 4; j++)
            crow[j] = silu(acc1[i][j]) * acc3[i][j];
    }
}

// ---------------- single GEMM: C = A@B ---------------------------------------
// BM=128, BN=128, BK=16; 256 threads; thread tile 8x8 (split-n for bank safety)
// SCATTER=false: A=g_hs, B=ws2, plain store to out   (N=DD, K=HSS)
// SCATTER=true : A=g_hid[e], B=w2[e], atomicAdd wt*val into out (N=DD, K=HH)
template<bool SCATTER>
__global__ __launch_bounds__(256, 2)
void gemm_single_kernel(const float* __restrict__ Ball,
                        float* __restrict__ out,
                        int N, int Kd) {
    int e = SCATTER ? blockIdx.z : 0;
    int M;
    const float* A;
    const float* B;
    const int* tok = nullptr;
    const float* wt = nullptr;
    if (SCATTER) {
        M = g_cnt[e];
        A = g_hid + (size_t)e * TT * HH;
        B = Ball + (size_t)e * Kd * N;
        tok = g_tok + e * TT;
        wt  = g_wt  + e * TT;
    } else {
        M = TT;
        A = g_hs;
        B = Ball;
    }

    int m0 = blockIdx.y * 128;
    int n0 = blockIdx.x * 128;
    if (m0 >= M) return;

    __shared__ float As[16][128];
    __shared__ float Bs[16][128];

    int tid = threadIdx.x;
    int tx = tid & 15;
    int ty = tid >> 4;

    float acc[8][8];
    #pragma unroll
    for (int i = 0; i < 8; i++)
        #pragma unroll
        for (int j = 0; j < 8; j++) acc[i][j] = 0.f;

    int am0 = tid >> 2;
    int am1 = am0 + 64;
    int ak  = (tid & 3) * 4;
    int r0 = m0 + am0, r1 = m0 + am1;
    bool v0 = r0 < M, v1 = r1 < M;
    const float* arow0 = A + (size_t)(v0 ? r0 : 0) * Kd;
    const float* arow1 = A + (size_t)(v1 ? r1 : 0) * Kd;

    int bk = tid >> 5;            // 0..7 (+8 for second load)
    int bn = (tid & 31) * 4;

    for (int k0 = 0; k0 < Kd; k0 += 16) {
        float4 a0 = v0 ? *(const float4*)(arow0 + k0 + ak) : make_float4(0, 0, 0, 0);
        float4 a1 = v1 ? *(const float4*)(arow1 + k0 + ak) : make_float4(0, 0, 0, 0);
        As[ak + 0][am0] = a0.x; As[ak + 1][am0] = a0.y;
        As[ak + 2][am0] = a0.z; As[ak + 3][am0] = a0.w;
        As[ak + 0][am1] = a1.x; As[ak + 1][am1] = a1.y;
        As[ak + 2][am1] = a1.z; As[ak + 3][am1] = a1.w;
        *(float4*)&Bs[bk][bn]     = *(const float4*)(B + (size_t)(k0 + bk) * N + n0 + bn);
        *(float4*)&Bs[bk + 8][bn] = *(const float4*)(B + (size_t)(k0 + bk + 8) * N + n0 + bn);
        __syncthreads();
        #pragma unroll
        for (int k = 0; k < 16; k++) {
            float4 aA = *(const float4*)&As[k][ty * 8];
            float4 aB = *(const float4*)&As[k][ty * 8 + 4];
            float4 b0 = *(const float4*)&Bs[k][tx * 4];        // n block 0
            float4 b1 = *(const float4*)&Bs[k][64 + tx * 4];   // n block 1
            float a[8] = {aA.x, aA.y, aA.z, aA.w, aB.x, aB.y, aB.z, aB.w};
            float bb[8] = {b0.x, b0.y, b0.z, b0.w, b1.x, b1.y, b1.z, b1.w};
            #pragma unroll
            for (int i = 0; i < 8; i++)
                #pragma unroll
                for (int j = 0; j < 8; j++)
                    acc[i][j] += a[i] * bb[j];
        }
        __syncthreads();
    }

    #pragma unroll
    for (int i = 0; i < 8; i++) {
        int m = m0 + ty * 8 + i;
        if (m >= M) continue;
        if (SCATTER) {
            int t = tok[m];
            float w = wt[m];
            float* orow = out + (size_t)t * N;
            #pragma unroll
            for (int j = 0; j < 4; j++)
                atomicAdd(&orow[n0 + tx * 4 + j], w * acc[i][j]);
            #pragma unroll
            for (int j = 0; j < 4; j++)
                atomicAdd(&orow[n0 + 64 + tx * 4 + j], w * acc[i][j + 4]);
        } else {
            float* orow = out + (size_t)m * N;
            #pragma unroll
            for (int j = 0; j < 4; j++)
                orow[n0 + tx * 4 + j] = acc[i][j];
            #pragma unroll
            for (int j = 0; j < 4; j++)
                orow[n0 + 64 + tx * 4 + j] = acc[i][j + 4];
        }
    }
}

// ---------------- launch -----------------------------------------------------
extern "C" void kernel_launch(void* const* d_in, const int* in_sizes, int n_in,
                              void* d_out, int out_size) {
    const float* x   = (const float*)d_in[0];
    const float* gw  = (const float*)d_in[1];
    const float* w1  = (const float*)d_in[2];
    const float* w3  = (const float*)d_in[3];
    const float* w2  = (const float*)d_in[4];
    const float* ws1 = (const float*)d_in[5];
    const float* ws3 = (const float*)d_in[6];
    const float* ws2 = (const float*)d_in[7];
    float* out = (float*)d_out;

    init_kernel<<<1, 32>>>();
    router_kernel<<<TT / 8, 256>>>(x, gw);

    // shared expert: GLU then down-proj (plain store establishes out base)
    {
        dim3 g(HSS / 64, TT / 128, 1);
        gemm_glu_kernel<false><<<g, 256>>>(x, ws1, ws3, HSS, DD);
    }
    {
        dim3 g(DD / 128, TT / 128, 1);
        gemm_single_kernel<false><<<g, 256>>>(ws2, out, DD, HSS);
    }

    // routed experts: gathered GLU, then weighted atomic scatter down-proj
    {
        dim3 g(HH / 64, TT / 128, EE);
        gemm_glu_kernel<true><<<g, 256>>>(x, w1, w3, HH, DD);
    }
    {
        dim3 g(DD / 128, TT / 128, EE);
        gemm_single_kernel<true><<<g, 256>>>(w2, out, DD, HH);
    }
}

// round 7
// speedup vs baseline: 2.6000x; 2.6000x over previous
#include <cuda_runtime.h>
#include <math.h>
#include <stdint.h>

#define TT  2048
#define DD  1024
#define HH  512
#define HSS 1024
#define EE  8
#define BK  16
#define NST 3

#define GLU_STGF 4352                 // floats: As 2048 + Ws1 1152 + Ws3 1152
#define GLU_SMEMB (NST * GLU_STGF * 4)
#define DN_STGF  4224                 // floats: As 2048 + Ws 2176
#define DN_SMEMB  (NST * DN_STGF * 4)

// ---------------- scratch ----------------------------------------------------
__device__ float g_hid[(size_t)EE * TT * HH];
__device__ float g_hs [(size_t)TT * HSS];
__device__ int   g_cnt[EE];
__device__ int   g_tok[EE * TT];
__device__ float g_wt [EE * TT];

// ---------------- helpers ----------------------------------------------------
__device__ __forceinline__ uint32_t smem_u32(const void* p) {
    uint32_t a;
    asm("{ .reg .u64 t; cvta.to.shared.u64 t, %1; cvt.u32.u64 %0, t; }" : "=r"(a) : "l"(p));
    return a;
}
#define CP16(dst, src) \
    asm volatile("cp.async.cg.shared.global [%0], [%1], 16;" :: "r"((uint32_t)(dst)), "l"(src))
#define CP_COMMIT() asm volatile("cp.async.commit_group;" ::: "memory")
#define CP_WAIT1()  asm volatile("cp.async.wait_group 1;" ::: "memory")

__device__ __forceinline__ uint32_t f2tf(float f) {
    uint32_t r;
    asm("cvt.rna.tf32.f32 %0, %1;" : "=r"(r) : "f"(f));
    return r;
}
__device__ __forceinline__ void mma8(float* c, const uint32_t* a, const uint32_t* b) {
    asm volatile(
        "mma.sync.aligned.m16n8k8.row.col.f32.tf32.tf32.f32 "
        "{%0,%1,%2,%3}, {%4,%5,%6,%7}, {%8,%9}, {%0,%1,%2,%3};"
        : "+f"(c[0]), "+f"(c[1]), "+f"(c[2]), "+f"(c[3])
        : "r"(a[0]), "r"(a[1]), "r"(a[2]), "r"(a[3]), "r"(b[0]), "r"(b[1]));
}
// A-tile swizzled element offset: row m has 4 16B chunks, chunk c at (c + (m>>1)) & 3
__device__ __forceinline__ int aoff(int m, int k) {
    return m * 16 + (((k >> 2) + (m >> 1)) & 3) * 4 + (k & 3);
}
__device__ __forceinline__ float silu_f(float v) { return v / (1.f + expf(-v)); }

// ---------------- init + router ----------------------------------------------
__global__ void init_kernel() { if (threadIdx.x < EE) g_cnt[threadIdx.x] = 0; }

__global__ void router_kernel(const float* __restrict__ x, const float* __restrict__ gw) {
    int warp = (blockIdx.x * blockDim.x + threadIdx.x) >> 5;
    int lane = threadIdx.x & 31;
    if (warp >= TT) return;
    const float* xr = x + (size_t)warp * DD;
    float acc[EE];
    #pragma unroll
    for (int e = 0; e < EE; e++) acc[e] = 0.f;
    for (int d = lane; d < DD; d += 32) {
        float xv = xr[d];
        const float* g = gw + (size_t)d * EE;
        #pragma unroll
        for (int e = 0; e < EE; e++) acc[e] += xv * g[e];
    }
    #pragma unroll
    for (int e = 0; e < EE; e++) {
        #pragma unroll
        for (int o = 16; o > 0; o >>= 1) acc[e] += __shfl_xor_sync(0xFFFFFFFFu, acc[e], o);
    }
    if (lane == 0) {
        float s[EE];
        #pragma unroll
        for (int e = 0; e < EE; e++) s[e] = 1.f / (1.f + expf(-acc[e]));
        int i0 = 0;
        #pragma unroll
        for (int e = 1; e < EE; e++) if (s[e] > s[i0]) i0 = e;
        int i1 = (i0 == 0) ? 1 : 0;
        #pragma unroll
        for (int e = 0; e < EE; e++) { if (e != i0 && s[e] > s[i1]) i1 = e; }
        float sum = s[i0] + s[i1];
        int p0 = atomicAdd(&g_cnt[i0], 1);
        g_tok[i0 * TT + p0] = warp; g_wt[i0 * TT + p0] = s[i0] / sum;
        int p1 = atomicAdd(&g_cnt[i1], 1);
        g_tok[i1 * TT + p1] = warp; g_wt[i1 * TT + p1] = s[i1] / sum;
    }
}

// ---------------- fused SwiGLU GEMM (mma.sync tf32) -------------------------
// BM=128, BN=64, BK=16, 256 threads, 8 warps = 4(m) x 2(n), warp tile 32x32.
// z==0: shared (A=x, B=ws1/ws3 ld HSS, C=g_hs); z>=1: expert e (gathered A, ld HH)
__global__ __launch_bounds__(256)
void glu_tc(const float* __restrict__ x,
            const float* __restrict__ ws1, const float* __restrict__ ws3,
            const float* __restrict__ w1,  const float* __restrict__ w3) {
    extern __shared__ float sm[];
    const int tid = threadIdx.x;
    const int z = blockIdx.z, e = z - 1;

    int M, ldB, ldC;
    const float *B1, *B3;
    const int* tok = nullptr;
    float* C;
    if (z == 0) {
        M = TT; ldB = HSS; ldC = HSS;
        B1 = ws1; B3 = ws3; C = g_hs;
    } else {
        if (blockIdx.x >= HH / 64) return;
        M = g_cnt[e]; ldB = HH; ldC = HH;
        tok = g_tok + e * TT;
        B1 = w1 + (size_t)e * DD * HH;
        B3 = w3 + (size_t)e * DD * HH;
        C  = g_hid + (size_t)e * TT * HH;
    }
    const int m0 = blockIdx.y * 128, n0 = blockIdx.x * 64;
    if (m0 >= M) return;

    const uint32_t sb = smem_u32(sm);

    // producer setup: 2 A chunks + 1 chunk each of W1/W3 per thread per iter
    const float* aptr[2];
    uint32_t adst[2];
    #pragma unroll
    for (int i = 0; i < 2; i++) {
        int id = tid + i * 256;
        int am = id >> 2, ac = id & 3;
        int gm = m0 + am;
        int sr = (z == 0) ? gm : ((gm < M) ? tok[gm] : tok[m0]);
        aptr[i] = x + (size_t)sr * DD + ac * 4;
        adst[i] = sb + (uint32_t)(am * 16 + ((ac + (am >> 1)) & 3) * 4) * 4;
    }
    const int wk = tid >> 4, wn4 = (tid & 15) * 4;
    const float* b1p = B1 + (size_t)wk * ldB + n0 + wn4;
    const float* b3p = B3 + (size_t)wk * ldB + n0 + wn4;
    const uint32_t wdst = sb + (uint32_t)(2048 + wk * 72 + wn4) * 4;

    const int nit = DD / BK;  // 64

    auto load_stage = [&](int it) {
        if (it < nit) {
            uint32_t so = (uint32_t)(it % NST) * GLU_STGF * 4;
            int k0 = it * BK;
            CP16(adst[0] + so, aptr[0] + k0);
            CP16(adst[1] + so, aptr[1] + k0);
            size_t wko = (size_t)k0 * ldB;
            CP16(wdst + so,            b1p + wko);
            CP16(wdst + so + 1152 * 4, b3p + wko);
        }
        CP_COMMIT();
    };

    const int lane = tid & 31, wid = tid >> 5;
    const int g = lane >> 2, t = lane & 3;
    const int wm = wid >> 1, wn = wid & 1;
    float acc1[2][4][4] = {}, acc3[2][4][4] = {};

    for (int p = 0; p < NST - 1; p++) load_stage(p);

    for (int it = 0; it < nit; it++) {
        CP_WAIT1();
        __syncthreads();
        load_stage(it + NST - 1);
        const float* st = sm + (size_t)(it % NST) * GLU_STGF;
        #pragma unroll
        for (int k8 = 0; k8 < 16; k8 += 8) {
            uint32_t a[2][4];
            #pragma unroll
            for (int mf = 0; mf < 2; mf++) {
                int m = wm * 32 + mf * 16 + g;
                int k = k8 + t;
                a[mf][0] = f2tf(st[aoff(m, k)]);
                a[mf][1] = f2tf(st[aoff(m + 8, k)]);
                a[mf][2] = f2tf(st[aoff(m, k + 4)]);
                a[mf][3] = f2tf(st[aoff(m + 8, k + 4)]);
            }
            uint32_t b1[4][2], b3[4][2];
            #pragma unroll
            for (int nf = 0; nf < 4; nf++) {
                int n = wn * 32 + nf * 8 + g;
                b1[nf][0] = f2tf(st[2048 + (k8 + t) * 72 + n]);
                b1[nf][1] = f2tf(st[2048 + (k8 + t + 4) * 72 + n]);
                b3[nf][0] = f2tf(st[3200 + (k8 + t) * 72 + n]);
                b3[nf][1] = f2tf(st[3200 + (k8 + t + 4) * 72 + n]);
            }
            #pragma unroll
            for (int mf = 0; mf < 2; mf++)
                #pragma unroll
                for (int nf = 0; nf < 4; nf++) {
                    mma8(acc1[mf][nf], a[mf], b1[nf]);
                    mma8(acc3[mf][nf], a[mf], b3[nf]);
                }
        }
    }

    // epilogue: C = silu(acc1) * acc3
    #pragma unroll
    for (int mf = 0; mf < 2; mf++) {
        #pragma unroll
        for (int nf = 0; nf < 4; nf++) {
            int r0  = m0 + wm * 32 + mf * 16 + g;
            int col = n0 + wn * 32 + nf * 8 + t * 2;
            if (r0 < M) {
                float2 v;
                v.x = silu_f(acc1[mf][nf][0]) * acc3[mf][nf][0];
                v.y = silu_f(acc1[mf][nf][1]) * acc3[mf][nf][1];
                *(float2*)&C[(size_t)r0 * ldC + col] = v;
            }
            int r1 = r0 + 8;
            if (r1 < M) {
                float2 v;
                v.x = silu_f(acc1[mf][nf][2]) * acc3[mf][nf][2];
                v.y = silu_f(acc1[mf][nf][3]) * acc3[mf][nf][3];
                *(float2*)&C[(size_t)r1 * ldC + col] = v;
            }
        }
    }
}

// ---------------- down-proj GEMM (mma.sync tf32) -----------------------------
// BM=128, BN=128, BK=16, 256 threads, 8 warps = 2(m) x 4(n), warp tile 64x32.
// ROUTED=false: out[m][n] = g_hs @ ws2 (plain store)
// ROUTED=true : out[tok][n] += wt * (g_hid[e] @ w2[e])  (atomicAdd), e=blockIdx.z
template<bool ROUTED>
__global__ __launch_bounds__(256)
void down_tc(const float* __restrict__ W, float* __restrict__ out) {
    extern __shared__ float sm[];
    const int tid = threadIdx.x;
    const int e = ROUTED ? blockIdx.z : 0;

    int M, Kd;
    const float *A, *B;
    if (!ROUTED) { M = TT; Kd = HSS; A = g_hs; B = W; }
    else {
        M = g_cnt[e]; Kd = HH;
        A = g_hid + (size_t)e * TT * HH;
        B = W + (size_t)e * HH * DD;
    }
    const int m0 = blockIdx.y * 128, n0 = blockIdx.x * 128;
    if (m0 >= M) return;

    const uint32_t sb = smem_u32(sm);

    const float* aptr[2];
    uint32_t adst[2];
    #pragma unroll
    for (int i = 0; i < 2; i++) {
        int id = tid + i * 256;
        int am = id >> 2, ac = id & 3;
        int r = m0 + am;
        if (r >= M) r = m0;
        aptr[i] = A + (size_t)r * Kd + ac * 4;
        adst[i] = sb + (uint32_t)(am * 16 + ((ac + (am >> 1)) & 3) * 4) * 4;
    }
    const float* bptr[2];
    uint32_t bdst[2];
    #pragma unroll
    for (int i = 0; i < 2; i++) {
        int id = tid + i * 256;
        int k = id >> 5, nch = id & 31;
        bptr[i] = B + (size_t)k * DD + n0 + nch * 4;
        bdst[i] = sb + (uint32_t)(2048 + k * 136 + nch * 4) * 4;
    }
    const int nit = Kd / BK;  // 64 or 32

    auto load_stage = [&](int it) {
        if (it < nit) {
            uint32_t so = (uint32_t)(it % NST) * DN_STGF * 4;
            int k0 = it * BK;
            CP16(adst[0] + so, aptr[0] + k0);
            CP16(adst[1] + so, aptr[1] + k0);
            size_t wko = (size_t)k0 * DD;
            CP16(bdst[0] + so, bptr[0] + wko);
            CP16(bdst[1] + so, bptr[1] + wko);
        }
        CP_COMMIT();
    };

    const int lane = tid & 31, wid = tid >> 5;
    const int g = lane >> 2, t = lane & 3;
    const int wm = wid >> 2, wn = wid & 3;
    float acc[4][4][4] = {};

    for (int p = 0; p < NST - 1; p++) load_stage(p);

    for (int it = 0; it < nit; it++) {
        CP_WAIT1();
        __syncthreads();
        load_stage(it + NST - 1);
        const float* st = sm + (size_t)(it % NST) * DN_STGF;
        #pragma unroll
        for (int k8 = 0; k8 < 16; k8 += 8) {
            uint32_t a[4][4];
            #pragma unroll
            for (int mf = 0; mf < 4; mf++) {
                int m = wm * 64 + mf * 16 + g;
                int k = k8 + t;
                a[mf][0] = f2tf(st[aoff(m, k)]);
                a[mf][1] = f2tf(st[aoff(m + 8, k)]);
                a[mf][2] = f2tf(st[aoff(m, k + 4)]);
                a[mf][3] = f2tf(st[aoff(m + 8, k + 4)]);
            }
            uint32_t b[4][2];
            #pragma unroll
            for (int nf = 0; nf < 4; nf++) {
                int n = wn * 32 + nf * 8 + g;
                b[nf][0] = f2tf(st[2048 + (k8 + t) * 136 + n]);
                b[nf][1] = f2tf(st[2048 + (k8 + t + 4) * 136 + n]);
            }
            #pragma unroll
            for (int mf = 0; mf < 4; mf++)
                #pragma unroll
                for (int nf = 0; nf < 4; nf++)
                    mma8(acc[mf][nf], a[mf], b[nf]);
        }
    }

    #pragma unroll
    for (int mf = 0; mf < 4; mf++) {
        #pragma unroll
        for (int nf = 0; nf < 4; nf++) {
            int r0  = m0 + wm * 64 + mf * 16 + g;
            int col = n0 + wn * 32 + nf * 8 + t * 2;
            if (ROUTED) {
                if (r0 < M) {
                    int tk = g_tok[e * TT + r0];
                    float w = g_wt[e * TT + r0];
                    float* orow = out + (size_t)tk * DD + col;
                    atomicAdd(orow,     w * acc[mf][nf][0]);
                    atomicAdd(orow + 1, w * acc[mf][nf][1]);
                }
                int r1 = r0 + 8;
                if (r1 < M) {
                    int tk = g_tok[e * TT + r1];
                    float w = g_wt[e * TT + r1];
                    float* orow = out + (size_t)tk * DD + col;
                    atomicAdd(orow,     w * acc[mf][nf][2]);
                    atomicAdd(orow + 1, w * acc[mf][nf][3]);
                }
            } else {
                if (r0 < M) {
                    float2 v; v.x = acc[mf][nf][0]; v.y = acc[mf][nf][1];
                    *(float2*)&out[(size_t)r0 * DD + col] = v;
                }
                int r1 = r0 + 8;
                if (r1 < M) {
                    float2 v; v.x = acc[mf][nf][2]; v.y = acc[mf][nf][3];
                    *(float2*)&out[(size_t)r1 * DD + col] = v;
                }
            }
        }
    }
}

// ---------------- launch -----------------------------------------------------
extern "C" void kernel_launch(void* const* d_in, const int* in_sizes, int n_in,
                              void* d_out, int out_size) {
    (void)in_sizes; (void)n_in; (void)out_size;
    const float* x   = (const float*)d_in[0];
    const float* gw  = (const float*)d_in[1];
    const float* w1  = (const float*)d_in[2];
    const float* w3  = (const float*)d_in[3];
    const float* w2  = (const float*)d_in[4];
    const float* ws1 = (const float*)d_in[5];
    const float* ws3 = (const float*)d_in[6];
    const float* ws2 = (const float*)d_in[7];
    float* out = (float*)d_out;

    cudaFuncSetAttribute(glu_tc,         cudaFuncAttributeMaxDynamicSharedMemorySize, GLU_SMEMB);
    cudaFuncSetAttribute(down_tc<false>, cudaFuncAttributeMaxDynamicSharedMemorySize, DN_SMEMB);
    cudaFuncSetAttribute(down_tc<true>,  cudaFuncAttributeMaxDynamicSharedMemorySize, DN_SMEMB);

    init_kernel<<<1, 32>>>();
    router_kernel<<<TT / 8, 256>>>(x, gw);

    // fused SwiGLU for shared expert (z=0) + all routed experts (z=1..8)
    glu_tc<<<dim3(16, 16, 1 + EE), 256, GLU_SMEMB>>>(x, ws1, ws3, w1, w3);

    // down-proj: shared (plain store), then routed (weighted atomic accumulate)
    down_tc<false><<<dim3(8, 16, 1), 256, DN_SMEMB>>>(ws2, out);
    down_tc<true> <<<dim3(8, 16, EE), 256, DN_SMEMB>>>(w2, out);
}

// round 8
// speedup vs baseline: 2.6052x; 1.0020x over previous
#include <cuda_runtime.h>
#include <math.h>
#include <stdint.h>

#define TT  2048
#define DD  1024
#define HH  512
#define HSS 1024
#define EE  8
#define BK  16
#define NST 3

#define GLU_STGF 4352                 // floats: As 2048 + Ws1 1152 + Ws3 1152
#define GLU_SMEMB (NST * GLU_STGF * 4)
#define DN_STGF  4224                 // floats: As 2048 + Ws 2176
#define DN_SMEMB  (NST * DN_STGF * 4)

// ---------------- scratch ----------------------------------------------------
__device__ float g_hid[(size_t)EE * TT * HH];   // tf32-rounded GLU hidden
__device__ float g_hs [(size_t)TT * HSS];       // tf32-rounded shared hidden
__device__ float g_xr [(size_t)TT * DD];        // tf32-rounded input
__device__ float g_w1r[(size_t)EE * DD * HH];   // tf32-rounded weights
__device__ float g_w3r[(size_t)EE * DD * HH];
__device__ float g_w2r[(size_t)EE * HH * DD];
__device__ float g_ws1r[(size_t)DD * HSS];
__device__ float g_ws3r[(size_t)DD * HSS];
__device__ float g_ws2r[(size_t)HSS * DD];
__device__ int   g_cnt[EE];
__device__ int   g_tok[EE * TT];
__device__ float g_wt [EE * TT];

// ---------------- helpers ----------------------------------------------------
__device__ __forceinline__ uint32_t smem_u32(const void* p) {
    uint32_t a;
    asm("{ .reg .u64 t; cvta.to.shared.u64 t, %1; cvt.u32.u64 %0, t; }" : "=r"(a) : "l"(p));
    return a;
}
#define CP16(dst, src) \
    asm volatile("cp.async.cg.shared.global [%0], [%1], 16;" :: "r"((uint32_t)(dst)), "l"(src))
#define CP_COMMIT() asm volatile("cp.async.commit_group;" ::: "memory")
#define CP_WAIT1()  asm volatile("cp.async.wait_group 1;" ::: "memory")

__device__ __forceinline__ uint32_t f2tf(float f) {
    uint32_t r;
    asm("cvt.rna.tf32.f32 %0, %1;" : "=r"(r) : "f"(f));
    return r;
}
__device__ __forceinline__ void mma8(float* c, const uint32_t* a, const uint32_t* b) {
    asm volatile(
        "mma.sync.aligned.m16n8k8.row.col.f32.tf32.tf32.f32 "
        "{%0,%1,%2,%3}, {%4,%5,%6,%7}, {%8,%9}, {%0,%1,%2,%3};"
        : "+f"(c[0]), "+f"(c[1]), "+f"(c[2]), "+f"(c[3])
        : "r"(a[0]), "r"(a[1]), "r"(a[2]), "r"(a[3]), "r"(b[0]), "r"(b[1]));
}
// A-tile swizzled element offset: row m has 4 16B chunks, chunk c at (c + (m>>1)) & 3
__device__ __forceinline__ int aoff(int m, int k) {
    return m * 16 + (((k >> 2) + (m >> 1)) & 3) * 4 + (k & 3);
}
__device__ __forceinline__ float silu_f(float v) { return v / (1.f + expf(-v)); }

// ---------------- init / zero / cvt ------------------------------------------
__global__ void init_kernel() { if (threadIdx.x < EE) g_cnt[threadIdx.x] = 0; }

__global__ void zero_out_kernel(float* __restrict__ out) {
    int i = blockIdx.x * blockDim.x + threadIdx.x;
    float4 z = make_float4(0.f, 0.f, 0.f, 0.f);
    ((float4*)out)[i] = z;
}

__global__ void cvt_kernel(const float* __restrict__ src, float* __restrict__ dst, int n4) {
    int i = blockIdx.x * blockDim.x + threadIdx.x;
    int stride = gridDim.x * blockDim.x;
    for (; i < n4; i += stride) {
        float4 v = ((const float4*)src)[i];
        v.x = __uint_as_float(f2tf(v.x));
        v.y = __uint_as_float(f2tf(v.y));
        v.z = __uint_as_float(f2tf(v.z));
        v.w = __uint_as_float(f2tf(v.w));
        ((float4*)dst)[i] = v;
    }
}

// ---------------- router: scores + top-2 + rounded x copy --------------------
__global__ void router_kernel(const float* __restrict__ x, const float* __restrict__ gw) {
    int warp = (blockIdx.x * blockDim.x + threadIdx.x) >> 5;
    int lane = threadIdx.x & 31;
    if (warp >= TT) return;
    const float* xr = x + (size_t)warp * DD;
    float* xo = g_xr + (size_t)warp * DD;
    float acc[EE];
    #pragma unroll
    for (int e = 0; e < EE; e++) acc[e] = 0.f;
    for (int d = lane; d < DD; d += 32) {
        float xv = xr[d];
        xo[d] = __uint_as_float(f2tf(xv));
        const float* g = gw + (size_t)d * EE;
        #pragma unroll
        for (int e = 0; e < EE; e++) acc[e] += xv * g[e];
    }
    #pragma unroll
    for (int e = 0; e < EE; e++) {
        #pragma unroll
        for (int o = 16; o > 0; o >>= 1) acc[e] += __shfl_xor_sync(0xFFFFFFFFu, acc[e], o);
    }
    if (lane == 0) {
        float s[EE];
        #pragma unroll
        for (int e = 0; e < EE; e++) s[e] = 1.f / (1.f + expf(-acc[e]));
        int i0 = 0;
        #pragma unroll
        for (int e = 1; e < EE; e++) if (s[e] > s[i0]) i0 = e;
        int i1 = (i0 == 0) ? 1 : 0;
        #pragma unroll
        for (int e = 0; e < EE; e++) { if (e != i0 && s[e] > s[i1]) i1 = e; }
        float sum = s[i0] + s[i1];
        int p0 = atomicAdd(&g_cnt[i0], 1);
        g_tok[i0 * TT + p0] = warp; g_wt[i0 * TT + p0] = s[i0] / sum;
        int p1 = atomicAdd(&g_cnt[i1], 1);
        g_tok[i1 * TT + p1] = warp; g_wt[i1 * TT + p1] = s[i1] / sum;
    }
}

// ---------------- fused SwiGLU GEMM (mma.sync tf32, pre-rounded operands) ---
// BM=128, BN=64, BK=16, 256 threads, 8 warps = 4(m) x 2(n), warp tile 32x32.
// z==0: shared (A=g_xr, B=g_ws1r/g_ws3r ld HSS, C=g_hs); z>=1: expert e
__global__ __launch_bounds__(256, 2)
void glu_tc() {
    extern __shared__ float sm[];
    const int tid = threadIdx.x;
    const int z = blockIdx.z, e = z - 1;

    int M, ldB, ldC;
    const float *B1, *B3;
    const int* tok = nullptr;
    float* C;
    if (z == 0) {
        M = TT; ldB = HSS; ldC = HSS;
        B1 = g_ws1r; B3 = g_ws3r; C = g_hs;
    } else {
        if (blockIdx.x >= HH / 64) return;
        M = g_cnt[e]; ldB = HH; ldC = HH;
        tok = g_tok + e * TT;
        B1 = g_w1r + (size_t)e * DD * HH;
        B3 = g_w3r + (size_t)e * DD * HH;
        C  = g_hid + (size_t)e * TT * HH;
    }
    const int m0 = blockIdx.y * 128, n0 = blockIdx.x * 64;
    if (m0 >= M) return;

    const uint32_t sb = smem_u32(sm);

    const float* aptr[2];
    uint32_t adst[2];
    #pragma unroll
    for (int i = 0; i < 2; i++) {
        int id = tid + i * 256;
        int am = id >> 2, ac = id & 3;
        int gm = m0 + am;
        int sr = (z == 0) ? gm : ((gm < M) ? tok[gm] : tok[m0]);
        aptr[i] = g_xr + (size_t)sr * DD + ac * 4;
        adst[i] = sb + (uint32_t)(am * 16 + ((ac + (am >> 1)) & 3) * 4) * 4;
    }
    const int wk = tid >> 4, wn4 = (tid & 15) * 4;
    const float* b1p = B1 + (size_t)wk * ldB + n0 + wn4;
    const float* b3p = B3 + (size_t)wk * ldB + n0 + wn4;
    const uint32_t wdst = sb + (uint32_t)(2048 + wk * 72 + wn4) * 4;

    const int nit = DD / BK;  // 64

    auto load_stage = [&](int it) {
        if (it < nit) {
            uint32_t so = (uint32_t)(it % NST) * GLU_STGF * 4;
            int k0 = it * BK;
            CP16(adst[0] + so, aptr[0] + k0);
            CP16(adst[1] + so, aptr[1] + k0);
            size_t wko = (size_t)k0 * ldB;
            CP16(wdst + so,            b1p + wko);
            CP16(wdst + so + 1152 * 4, b3p + wko);
        }
        CP_COMMIT();
    };

    const int lane = tid & 31, wid = tid >> 5;
    const int g = lane >> 2, t = lane & 3;
    const int wm = wid >> 1, wn = wid & 1;
    float acc1[2][4][4] = {}, acc3[2][4][4] = {};

    for (int p = 0; p < NST - 1; p++) load_stage(p);

    for (int it = 0; it < nit; it++) {
        CP_WAIT1();
        __syncthreads();
        load_stage(it + NST - 1);
        const uint32_t* st = (const uint32_t*)(sm + (size_t)(it % NST) * GLU_STGF);
        #pragma unroll
        for (int k8 = 0; k8 < 16; k8 += 8) {
            uint32_t a[2][4];
            #pragma unroll
            for (int mf = 0; mf < 2; mf++) {
                int m = wm * 32 + mf * 16 + g;
                int k = k8 + t;
                a[mf][0] = st[aoff(m, k)];
                a[mf][1] = st[aoff(m + 8, k)];
                a[mf][2] = st[aoff(m, k + 4)];
                a[mf][3] = st[aoff(m + 8, k + 4)];
            }
            uint32_t b1[4][2], b3[4][2];
            #pragma unroll
            for (int nf = 0; nf < 4; nf++) {
                int n = wn * 32 + nf * 8 + g;
                b1[nf][0] = st[2048 + (k8 + t) * 72 + n];
                b1[nf][1] = st[2048 + (k8 + t + 4) * 72 + n];
                b3[nf][0] = st[3200 + (k8 + t) * 72 + n];
                b3[nf][1] = st[3200 + (k8 + t + 4) * 72 + n];
            }
            #pragma unroll
            for (int mf = 0; mf < 2; mf++)
                #pragma unroll
                for (int nf = 0; nf < 4; nf++) {
                    mma8(acc1[mf][nf], a[mf], b1[nf]);
                    mma8(acc3[mf][nf], a[mf], b3[nf]);
                }
        }
    }

    // epilogue: C = round_tf32(silu(acc1) * acc3)
    #pragma unroll
    for (int mf = 0; mf < 2; mf++) {
        #pragma unroll
        for (int nf = 0; nf < 4; nf++) {
            int r0  = m0 + wm * 32 + mf * 16 + g;
            int col = n0 + wn * 32 + nf * 8 + t * 2;
            if (r0 < M) {
                float2 v;
                v.x = __uint_as_float(f2tf(silu_f(acc1[mf][nf][0]) * acc3[mf][nf][0]));
                v.y = __uint_as_float(f2tf(silu_f(acc1[mf][nf][1]) * acc3[mf][nf][1]));
                *(float2*)&C[(size_t)r0 * ldC + col] = v;
            }
            int r1 = r0 + 8;
            if (r1 < M) {
                float2 v;
                v.x = __uint_as_float(f2tf(silu_f(acc1[mf][nf][2]) * acc3[mf][nf][2]));
                v.y = __uint_as_float(f2tf(silu_f(acc1[mf][nf][3]) * acc3[mf][nf][3]));
                *(float2*)&C[(size_t)r1 * ldC + col] = v;
            }
        }
    }
}

// ---------------- merged down-proj GEMM (atomicAdd into zeroed out) ----------
// BM=128, BN=128, BK=16, 256 threads, 8 warps = 2(m) x 4(n), warp tile 64x32.
// z==0: shared (A=g_hs, B=g_ws2r, w=1, token=m); z>=1: routed expert e=z-1
__global__ __launch_bounds__(256, 2)
void down_tc(float* __restrict__ out) {
    extern __shared__ float sm[];
    const int tid = threadIdx.x;
    const int z = blockIdx.z, e = z - 1;

    int M, Kd;
    const float *A, *B;
    if (z == 0) { M = TT; Kd = HSS; A = g_hs; B = g_ws2r; }
    else {
        M = g_cnt[e]; Kd = HH;
        A = g_hid + (size_t)e * TT * HH;
        B = g_w2r + (size_t)e * HH * DD;
    }
    const int m0 = blockIdx.y * 128, n0 = blockIdx.x * 128;
    if (m0 >= M) return;

    const uint32_t sb = smem_u32(sm);

    const float* aptr[2];
    uint32_t adst[2];
    #pragma unroll
    for (int i = 0; i < 2; i++) {
        int id = tid + i * 256;
        int am = id >> 2, ac = id & 3;
        int r = m0 + am;
        if (r >= M) r = m0;
        aptr[i] = A + (size_t)r * Kd + ac * 4;
        adst[i] = sb + (uint32_t)(am * 16 + ((ac + (am >> 1)) & 3) * 4) * 4;
    }
    const float* bptr[2];
    uint32_t bdst[2];
    #pragma unroll
    for (int i = 0; i < 2; i++) {
        int id = tid + i * 256;
        int k = id >> 5, nch = id & 31;
        bptr[i] = B + (size_t)k * DD + n0 + nch * 4;
        bdst[i] = sb + (uint32_t)(2048 + k * 136 + nch * 4) * 4;
    }
    const int nit = Kd / BK;  // 64 or 32

    auto load_stage = [&](int it) {
        if (it < nit) {
            uint32_t so = (uint32_t)(it % NST) * DN_STGF * 4;
            int k0 = it * BK;
            CP16(adst[0] + so, aptr[0] + k0);
            CP16(adst[1] + so, aptr[1] + k0);
            size_t wko = (size_t)k0 * DD;
            CP16(bdst[0] + so, bptr[0] + wko);
            CP16(bdst[1] + so, bptr[1] + wko);
        }
        CP_COMMIT();
    };

    const int lane = tid & 31, wid = tid >> 5;
    const int g = lane >> 2, t = lane & 3;
    const int wm = wid >> 2, wn = wid & 3;
    float acc[4][4][4] = {};

    for (int p = 0; p < NST - 1; p++) load_stage(p);

    for (int it = 0; it < nit; it++) {
        CP_WAIT1();
        __syncthreads();
        load_stage(it + NST - 1);
        const uint32_t* st = (const uint32_t*)(sm + (size_t)(it % NST) * DN_STGF);
        #pragma unroll
        for (int k8 = 0; k8 < 16; k8 += 8) {
            uint32_t a[4][4];
            #pragma unroll
            for (int mf = 0; mf < 4; mf++) {
                int m = wm * 64 + mf * 16 + g;
                int k = k8 + t;
                a[mf][0] = st[aoff(m, k)];
                a[mf][1] = st[aoff(m + 8, k)];
                a[mf][2] = st[aoff(m, k + 4)];
                a[mf][3] = st[aoff(m + 8, k + 4)];
            }
            uint32_t b[4][2];
            #pragma unroll
            for (int nf = 0; nf < 4; nf++) {
                int n = wn * 32 + nf * 8 + g;
                b[nf][0] = st[2048 + (k8 + t) * 136 + n];
                b[nf][1] = st[2048 + (k8 + t + 4) * 136 + n];
            }
            #pragma unroll
            for (int mf = 0; mf < 4; mf++)
                #pragma unroll
                for (int nf = 0; nf < 4; nf++)
                    mma8(acc[mf][nf], a[mf], b[nf]);
        }
    }

    #pragma unroll
    for (int mf = 0; mf < 4; mf++) {
        #pragma unroll
        for (int nf = 0; nf < 4; nf++) {
            int r0  = m0 + wm * 64 + mf * 16 + g;
            int col = n0 + wn * 32 + nf * 8 + t * 2;
            if (r0 < M) {
                int tk; float w;
                if (z == 0) { tk = r0; w = 1.f; }
                else        { tk = g_tok[e * TT + r0]; w = g_wt[e * TT + r0]; }
                float* orow = out + (size_t)tk * DD + col;
                atomicAdd(orow,     w * acc[mf][nf][0]);
                atomicAdd(orow + 1, w * acc[mf][nf][1]);
            }
            int r1 = r0 + 8;
            if (r1 < M) {
                int tk; float w;
                if (z == 0) { tk = r1; w = 1.f; }
                else        { tk = g_tok[e * TT + r1]; w = g_wt[e * TT + r1]; }
                float* orow = out + (size_t)tk * DD + col;
                atomicAdd(orow,     w * acc[mf][nf][2]);
                atomicAdd(orow + 1, w * acc[mf][nf][3]);
            }
        }
    }
}

// ---------------- launch -----------------------------------------------------
extern "C" void kernel_launch(void* const* d_in, const int* in_sizes, int n_in,
                              void* d_out, int out_size) {
    (void)in_sizes; (void)n_in; (void)out_size;
    const float* x   = (const float*)d_in[0];
    const float* gw  = (const float*)d_in[1];
    const float* w1  = (const float*)d_in[2];
    const float* w3  = (const float*)d_in[3];
    const float* w2  = (const float*)d_in[4];
    const float* ws1 = (const float*)d_in[5];
    const float* ws3 = (const float*)d_in[6];
    const float* ws2 = (const float*)d_in[7];
    float* out = (float*)d_out;

    cudaFuncSetAttribute(glu_tc,  cudaFuncAttributeMaxDynamicSharedMemorySize, GLU_SMEMB);
    cudaFuncSetAttribute(down_tc, cudaFuncAttributeMaxDynamicSharedMemorySize, DN_SMEMB);

    float *w1r, *w3r, *w2r, *ws1r, *ws3r, *ws2r;
    cudaGetSymbolAddress((void**)&w1r,  g_w1r);
    cudaGetSymbolAddress((void**)&w3r,  g_w3r);
    cudaGetSymbolAddress((void**)&w2r,  g_w2r);
    cudaGetSymbolAddress((void**)&ws1r, g_ws1r);
    cudaGetSymbolAddress((void**)&ws3r, g_ws3r);
    cudaGetSymbolAddress((void**)&ws2r, g_ws2r);

    init_kernel<<<1, 32>>>();
    zero_out_kernel<<<(TT * DD / 4) / 256, 256>>>(out);
    router_kernel<<<TT / 8, 256>>>(x, gw);

    cvt_kernel<<<592, 256>>>(w1,  w1r,  EE * DD * HH / 4);
    cvt_kernel<<<592, 256>>>(w3,  w3r,  EE * DD * HH / 4);
    cvt_kernel<<<592, 256>>>(w2,  w2r,  EE * HH * DD / 4);
    cvt_kernel<<<592, 256>>>(ws1, ws1r, DD * HSS / 4);
    cvt_kernel<<<592, 256>>>(ws3, ws3r, DD * HSS / 4);
    cvt_kernel<<<592, 256>>>(ws2, ws2r, HSS * DD / 4);

    // fused SwiGLU: shared expert (z=0) + routed experts (z=1..8)
    glu_tc<<<dim3(16, 16, 1 + EE), 256, GLU_SMEMB>>>();

    // merged down-proj: all contributions atomically accumulated
    down_tc<<<dim3(8, 16, 1 + EE), 256, DN_SMEMB>>>(out);
}

// round 9
// speedup vs baseline: 4.2466x; 1.6301x over previous
#include <cuda_runtime.h>
#include <cuda_fp16.h>
#include <math.h>
#include <stdint.h>

#define TT  2048
#define DD  1024
#define HH  512
#define HSS 1024
#define EE  8
#define BK  32
#define NST 3

// stage sizes in halves
#define GLU_STGH 8704                  // A 128x32 = 4096, B1 32x72 = 2304, B3 2304
#define GLU_SMEMB (NST * GLU_STGH * 2) // 52224 B
#define DN_STGH  8448                  // A 4096, B 32x136 = 4352
#define DN_SMEMB  (NST * DN_STGH * 2)  // 50688 B

// ---------------- scratch ----------------------------------------------------
__device__ __half g_xh  [(size_t)TT * DD];        // fp16 input
__device__ __half g_hsh [(size_t)TT * HSS];       // fp16 shared hidden
__device__ __half g_hidh[(size_t)EE * TT * HH];   // fp16 routed hidden
__device__ __half g_w1h [(size_t)EE * DD * HH];
__device__ __half g_w3h [(size_t)EE * DD * HH];
__device__ __half g_w2h [(size_t)EE * HH * DD];
__device__ __half g_ws1h[(size_t)DD * HSS];
__device__ __half g_ws3h[(size_t)DD * HSS];
__device__ __half g_ws2h[(size_t)HSS * DD];
__device__ int    g_cnt[EE];
__device__ int    g_tok[EE * TT];
__device__ float  g_wt [EE * TT];

// ---------------- helpers ----------------------------------------------------
__device__ __forceinline__ uint32_t smem_u32(const void* p) {
    uint32_t a;
    asm("{ .reg .u64 t; cvta.to.shared.u64 t, %1; cvt.u32.u64 %0, t; }" : "=r"(a) : "l"(p));
    return a;
}
#define CP16(dst, src) \
    asm volatile("cp.async.cg.shared.global [%0], [%1], 16;" :: "r"((uint32_t)(dst)), "l"(src))
#define CP_COMMIT() asm volatile("cp.async.commit_group;" ::: "memory")
#define CP_WAIT1()  asm volatile("cp.async.wait_group 1;" ::: "memory")

#define LDSM4(r0, r1, r2, r3, addr) \
    asm volatile("ldmatrix.sync.aligned.m8n8.x4.shared.b16 {%0,%1,%2,%3}, [%4];" \
        : "=r"(r0), "=r"(r1), "=r"(r2), "=r"(r3) : "r"(addr))
#define LDSM4T(r0, r1, r2, r3, addr) \
    asm volatile("ldmatrix.sync.aligned.m8n8.x4.trans.shared.b16 {%0,%1,%2,%3}, [%4];" \
        : "=r"(r0), "=r"(r1), "=r"(r2), "=r"(r3) : "r"(addr))

__device__ __forceinline__ void mmah(float* c, const uint32_t* a, uint32_t b0, uint32_t b1) {
    asm volatile(
        "mma.sync.aligned.m16n8k16.row.col.f32.f16.f16.f32 "
        "{%0,%1,%2,%3}, {%4,%5,%6,%7}, {%8,%9}, {%0,%1,%2,%3};"
        : "+f"(c[0]), "+f"(c[1]), "+f"(c[2]), "+f"(c[3])
        : "r"(a[0]), "r"(a[1]), "r"(a[2]), "r"(a[3]), "r"(b0), "r"(b1));
}
__device__ __forceinline__ float silu_f(float v) { return v / (1.f + expf(-v)); }

// ---------------- init / zero / cvt ------------------------------------------
__global__ void init_kernel() { if (threadIdx.x < EE) g_cnt[threadIdx.x] = 0; }

__global__ void zero_out_kernel(float* __restrict__ out) {
    int i = blockIdx.x * blockDim.x + threadIdx.x;
    ((float4*)out)[i] = make_float4(0.f, 0.f, 0.f, 0.f);
}

// fp32 -> fp16 (round-to-nearest)
__global__ void cvt_half_kernel(const float* __restrict__ src, __half* __restrict__ dst, int n4) {
    int i = blockIdx.x * blockDim.x + threadIdx.x;
    int stride = gridDim.x * blockDim.x;
    for (; i < n4; i += stride) {
        float4 v = ((const float4*)src)[i];
        half2 lo = __floats2half2_rn(v.x, v.y);
        half2 hi = __floats2half2_rn(v.z, v.w);
        ((half2*)dst)[i * 2]     = lo;
        ((half2*)dst)[i * 2 + 1] = hi;
    }
}

// ---------------- router: scores + top-2 + fp16 x copy -----------------------
__global__ void router_kernel(const float* __restrict__ x, const float* __restrict__ gw) {
    int warp = (blockIdx.x * blockDim.x + threadIdx.x) >> 5;
    int lane = threadIdx.x & 31;
    if (warp >= TT) return;
    const float* xr = x + (size_t)warp * DD;
    __half* xo = g_xh + (size_t)warp * DD;
    float acc[EE];
    #pragma unroll
    for (int e = 0; e < EE; e++) acc[e] = 0.f;
    for (int d = lane; d < DD; d += 32) {
        float xv = xr[d];
        xo[d] = __float2half_rn(xv);
        const float* g = gw + (size_t)d * EE;
        #pragma unroll
        for (int e = 0; e < EE; e++) acc[e] += xv * g[e];
    }
    #pragma unroll
    for (int e = 0; e < EE; e++) {
        #pragma unroll
        for (int o = 16; o > 0; o >>= 1) acc[e] += __shfl_xor_sync(0xFFFFFFFFu, acc[e], o);
    }
    if (lane == 0) {
        float s[EE];
        #pragma unroll
        for (int e = 0; e < EE; e++) s[e] = 1.f / (1.f + expf(-acc[e]));
        int i0 = 0;
        #pragma unroll
        for (int e = 1; e < EE; e++) if (s[e] > s[i0]) i0 = e;
        int i1 = (i0 == 0) ? 1 : 0;
        #pragma unroll
        for (int e = 0; e < EE; e++) { if (e != i0 && s[e] > s[i1]) i1 = e; }
        float sum = s[i0] + s[i1];
        int p0 = atomicAdd(&g_cnt[i0], 1);
        g_tok[i0 * TT + p0] = warp; g_wt[i0 * TT + p0] = s[i0] / sum;
        int p1 = atomicAdd(&g_cnt[i1], 1);
        g_tok[i1 * TT + p1] = warp; g_wt[i1 * TT + p1] = s[i1] / sum;
    }
}

// ---------------- fused SwiGLU GEMM (fp16 mma + ldmatrix) --------------------
// BM=128, BN=64, BK=32, 256 threads, 8 warps = 4(m) x 2(n), warp tile 32x32.
// z==0: shared (A=g_xh, B=g_ws1h/g_ws3h ld HSS, C=g_hsh); z>=1: expert e=z-1
__global__ __launch_bounds__(256, 2)
void glu_tc() {
    extern __shared__ __half smh[];
    const int tid = threadIdx.x;
    const int z = blockIdx.z, e = z - 1;

    int M, ldB, ldC;
    const __half *B1, *B3;
    const int* tok = nullptr;
    __half* C;
    if (z == 0) {
        M = TT; ldB = HSS; ldC = HSS;
        B1 = g_ws1h; B3 = g_ws3h; C = g_hsh;
    } else {
        if (blockIdx.x >= HH / 64) return;
        M = g_cnt[e]; ldB = HH; ldC = HH;
        tok = g_tok + e * TT;
        B1 = g_w1h + (size_t)e * DD * HH;
        B3 = g_w3h + (size_t)e * DD * HH;
        C  = g_hidh + (size_t)e * TT * HH;
    }
    const int m0 = blockIdx.y * 128, n0 = blockIdx.x * 64;
    if (m0 >= M) return;

    const uint32_t sb = smem_u32(smh);

    // producers: A 2 chunks (16B = 8 halves), B1/B3 1 chunk each, per stage
    const __half* aptr[2];
    uint32_t adst[2];
    #pragma unroll
    for (int i = 0; i < 2; i++) {
        int id = tid + i * 256;
        int am = id >> 2, ac = id & 3;                 // row 0..127, chunk 0..3
        int gm = m0 + am;
        int sr = (z == 0) ? gm : ((gm < M) ? tok[gm] : tok[m0]);
        aptr[i] = g_xh + (size_t)sr * DD + ac * 8;
        adst[i] = sb + (uint32_t)(am * 32 + ((ac ^ ((am >> 1) & 3)) * 8)) * 2;
    }
    const int bk = tid >> 3, bch = tid & 7;            // row 0..31, chunk 0..7
    const __half* b1p = B1 + (size_t)bk * ldB + n0 + bch * 8;
    const __half* b3p = B3 + (size_t)bk * ldB + n0 + bch * 8;
    const uint32_t bdst = sb + (uint32_t)(4096 + bk * 72 + bch * 8) * 2;

    const int nit = DD / BK;  // 32

    auto load_stage = [&](int it) {
        if (it < nit) {
            uint32_t so = (uint32_t)(it % NST) * GLU_STGH * 2;
            int k0 = it * BK;
            CP16(adst[0] + so, aptr[0] + k0);
            CP16(adst[1] + so, aptr[1] + k0);
            size_t wko = (size_t)k0 * ldB;
            CP16(bdst + so,            b1p + wko);
            CP16(bdst + so + 2304 * 2, b3p + wko);
        }
        CP_COMMIT();
    };

    const int lane = tid & 31, wid = tid >> 5;
    const int g = lane >> 2, t = lane & 3;
    const int wm = wid >> 1, wn = wid & 1;
    const int hi = lane >> 4;          // 0: k-lo half, 1: k-hi half

    // precompute per-lane ldmatrix byte offsets (within stage)
    uint32_t aoffb[2][2];              // [mf][s]
    #pragma unroll
    for (int mf = 0; mf < 2; mf++) {
        int row = wm * 32 + mf * 16 + (lane & 15);
        #pragma unroll
        for (int s = 0; s < 2; s++) {
            int chunk = (s * 2 + hi) ^ ((row >> 1) & 3);
            aoffb[mf][s] = (uint32_t)(row * 32 + chunk * 8) * 2;
        }
    }
    uint32_t boffb[2][2];              // [nt][s] (B1; B3 = +2304*2)
    #pragma unroll
    for (int nt = 0; nt < 2; nt++) {
        int n_off = wn * 32 + nt * 16 + hi * 8;
        #pragma unroll
        for (int s = 0; s < 2; s++) {
            int kl = s * 16 + ((lane >> 3) & 1) * 8 + (lane & 7);
            boffb[nt][s] = (uint32_t)(4096 + kl * 72 + n_off) * 2;
        }
    }

    float acc1[2][4][4] = {}, acc3[2][4][4] = {};

    for (int p = 0; p < NST - 1; p++) load_stage(p);

    for (int it = 0; it < nit; it++) {
        CP_WAIT1();
        __syncthreads();
        load_stage(it + NST - 1);
        uint32_t stb = sb + (uint32_t)(it % NST) * GLU_STGH * 2;
        #pragma unroll
        for (int s = 0; s < 2; s++) {
            uint32_t a[2][4], b1r[2][4], b3r[2][4];
            #pragma unroll
            for (int mf = 0; mf < 2; mf++)
                LDSM4(a[mf][0], a[mf][1], a[mf][2], a[mf][3], stb + aoffb[mf][s]);
            #pragma unroll
            for (int nt = 0; nt < 2; nt++) {
                LDSM4T(b1r[nt][0], b1r[nt][1], b1r[nt][2], b1r[nt][3], stb + boffb[nt][s]);
                LDSM4T(b3r[nt][0], b3r[nt][1], b3r[nt][2], b3r[nt][3], stb + boffb[nt][s] + 2304 * 2);
            }
            #pragma unroll
            for (int mf = 0; mf < 2; mf++)
                #pragma unroll
                for (int nf = 0; nf < 4; nf++) {
                    mmah(acc1[mf][nf], a[mf], b1r[nf >> 1][(nf & 1) * 2], b1r[nf >> 1][(nf & 1) * 2 + 1]);
                    mmah(acc3[mf][nf], a[mf], b3r[nf >> 1][(nf & 1) * 2], b3r[nf >> 1][(nf & 1) * 2 + 1]);
                }
        }
    }

    // epilogue: C = fp16(silu(acc1) * acc3)
    #pragma unroll
    for (int mf = 0; mf < 2; mf++) {
        #pragma unroll
        for (int nf = 0; nf < 4; nf++) {
            int r0  = m0 + wm * 32 + mf * 16 + g;
            int col = n0 + wn * 32 + nf * 8 + t * 2;
            if (r0 < M) {
                half2 v = __floats2half2_rn(silu_f(acc1[mf][nf][0]) * acc3[mf][nf][0],
                                            silu_f(acc1[mf][nf][1]) * acc3[mf][nf][1]);
                *(half2*)&C[(size_t)r0 * ldC + col] = v;
            }
            int r1 = r0 + 8;
            if (r1 < M) {
                half2 v = __floats2half2_rn(silu_f(acc1[mf][nf][2]) * acc3[mf][nf][2],
                                            silu_f(acc1[mf][nf][3]) * acc3[mf][nf][3]);
                *(half2*)&C[(size_t)r1 * ldC + col] = v;
            }
        }
    }
}

// ---------------- merged down-proj GEMM (fp16 mma + ldmatrix) ----------------
// BM=128, BN=128, BK=32, 256 threads, 8 warps = 2(m) x 4(n), warp tile 64x32.
// z==0: shared (A=g_hsh, B=g_ws2h, w=1, token=m); z>=1: routed expert e=z-1
__global__ __launch_bounds__(256, 2)
void down_tc(float* __restrict__ out) {
    extern __shared__ __half smh[];
    const int tid = threadIdx.x;
    const int z = blockIdx.z, e = z - 1;

    int M, Kd;
    const __half *A, *B;
    if (z == 0) { M = TT; Kd = HSS; A = g_hsh; B = g_ws2h; }
    else {
        M = g_cnt[e]; Kd = HH;
        A = g_hidh + (size_t)e * TT * HH;
        B = g_w2h + (size_t)e * HH * DD;
    }
    const int m0 = blockIdx.y * 128, n0 = blockIdx.x * 128;
    if (m0 >= M) return;

    const uint32_t sb = smem_u32(smh);

    const __half* aptr[2];
    uint32_t adst[2];
    #pragma unroll
    for (int i = 0; i < 2; i++) {
        int id = tid + i * 256;
        int am = id >> 2, ac = id & 3;
        int r = m0 + am;
        if (r >= M) r = m0;
        aptr[i] = A + (size_t)r * Kd + ac * 8;
        adst[i] = sb + (uint32_t)(am * 32 + ((ac ^ ((am >> 1) & 3)) * 8)) * 2;
    }
    const __half* bptr[2];
    uint32_t bdst[2];
    #pragma unroll
    for (int i = 0; i < 2; i++) {
        int id = tid + i * 256;
        int k = id >> 4, nch = id & 15;                // row 0..31, chunk 0..15
        bptr[i] = B + (size_t)k * DD + n0 + nch * 8;
        bdst[i] = sb + (uint32_t)(4096 + k * 136 + nch * 8) * 2;
    }
    const int nit = Kd / BK;  // 32 or 16

    auto load_stage = [&](int it) {
        if (it < nit) {
            uint32_t so = (uint32_t)(it % NST) * DN_STGH * 2;
            int k0 = it * BK;
            CP16(adst[0] + so, aptr[0] + k0);
            CP16(adst[1] + so, aptr[1] + k0);
            size_t wko = (size_t)k0 * DD;
            CP16(bdst[0] + so, bptr[0] + wko);
            CP16(bdst[1] + so, bptr[1] + wko);
        }
        CP_COMMIT();
    };

    const int lane = tid & 31, wid = tid >> 5;
    const int g = lane >> 2, t = lane & 3;
    const int wm = wid >> 2, wn = wid & 3;
    const int hi = lane >> 4;

    uint32_t aoffb[4][2];              // [mf][s]
    #pragma unroll
    for (int mf = 0; mf < 4; mf++) {
        int row = wm * 64 + mf * 16 + (lane & 15);
        #pragma unroll
        for (int s = 0; s < 2; s++) {
            int chunk = (s * 2 + hi) ^ ((row >> 1) & 3);
            aoffb[mf][s] = (uint32_t)(row * 32 + chunk * 8) * 2;
        }
    }
    uint32_t boffb[2][2];              // [nt][s]
    #pragma unroll
    for (int nt = 0; nt < 2; nt++) {
        int n_off = wn * 32 + nt * 16 + hi * 8;
        #pragma unroll
        for (int s = 0; s < 2; s++) {
            int kl = s * 16 + ((lane >> 3) & 1) * 8 + (lane & 7);
            boffb[nt][s] = (uint32_t)(4096 + kl * 136 + n_off) * 2;
        }
    }

    float acc[4][4][4] = {};

    for (int p = 0; p < NST - 1; p++) load_stage(p);

    for (int it = 0; it < nit; it++) {
        CP_WAIT1();
        __syncthreads();
        load_stage(it + NST - 1);
        uint32_t stb = sb + (uint32_t)(it % NST) * DN_STGH * 2;
        #pragma unroll
        for (int s = 0; s < 2; s++) {
            uint32_t a[4][4], br[2][4];
            #pragma unroll
            for (int mf = 0; mf < 4; mf++)
                LDSM4(a[mf][0], a[mf][1], a[mf][2], a[mf][3], stb + aoffb[mf][s]);
            #pragma unroll
            for (int nt = 0; nt < 2; nt++)
                LDSM4T(br[nt][0], br[nt][1], br[nt][2], br[nt][3], stb + boffb[nt][s]);
            #pragma unroll
            for (int mf = 0; mf < 4; mf++)
                #pragma unroll
                for (int nf = 0; nf < 4; nf++)
                    mmah(acc[mf][nf], a[mf], br[nf >> 1][(nf & 1) * 2], br[nf >> 1][(nf & 1) * 2 + 1]);
        }
    }

    #pragma unroll
    for (int mf = 0; mf < 4; mf++) {
        #pragma unroll
        for (int nf = 0; nf < 4; nf++) {
            int r0  = m0 + wm * 64 + mf * 16 + g;
            int col = n0 + wn * 32 + nf * 8 + t * 2;
            if (r0 < M) {
                int tk; float w;
                if (z == 0) { tk = r0; w = 1.f; }
                else        { tk = g_tok[e * TT + r0]; w = g_wt[e * TT + r0]; }
                float* orow = out + (size_t)tk * DD + col;
                atomicAdd(orow,     w * acc[mf][nf][0]);
                atomicAdd(orow + 1, w * acc[mf][nf][1]);
            }
            int r1 = r0 + 8;
            if (r1 < M) {
                int tk; float w;
                if (z == 0) { tk = r1; w = 1.f; }
                else        { tk = g_tok[e * TT + r1]; w = g_wt[e * TT + r1]; }
                float* orow = out + (size_t)tk * DD + col;
                atomicAdd(orow,     w * acc[mf][nf][2]);
                atomicAdd(orow + 1, w * acc[mf][nf][3]);
            }
        }
    }
}

// ---------------- launch -----------------------------------------------------
extern "C" void kernel_launch(void* const* d_in, const int* in_sizes, int n_in,
                              void* d_out, int out_size) {
    (void)in_sizes; (void)n_in; (void)out_size;
    const float* x   = (const float*)d_in[0];
    const float* gw  = (const float*)d_in[1];
    const float* w1  = (const float*)d_in[2];
    const float* w3  = (const float*)d_in[3];
    const float* w2  = (const float*)d_in[4];
    const float* ws1 = (const float*)d_in[5];
    const float* ws3 = (const float*)d_in[6];
    const float* ws2 = (const float*)d_in[7];
    float* out = (float*)d_out;

    cudaFuncSetAttribute(glu_tc,  cudaFuncAttributeMaxDynamicSharedMemorySize, GLU_SMEMB);
    cudaFuncSetAttribute(down_tc, cudaFuncAttributeMaxDynamicSharedMemorySize, DN_SMEMB);

    __half *w1h, *w3h, *w2h, *ws1h, *ws3h, *ws2h;
    cudaGetSymbolAddress((void**)&w1h,  g_w1h);
    cudaGetSymbolAddress((void**)&w3h,  g_w3h);
    cudaGetSymbolAddress((void**)&w2h,  g_w2h);
    cudaGetSymbolAddress((void**)&ws1h, g_ws1h);
    cudaGetSymbolAddress((void**)&ws3h, g_ws3h);
    cudaGetSymbolAddress((void**)&ws2h, g_ws2h);

    init_kernel<<<1, 32>>>();
    zero_out_kernel<<<(TT * DD / 4) / 256, 256>>>(out);
    router_kernel<<<TT / 8, 256>>>(x, gw);

    cvt_half_kernel<<<592, 256>>>(w1,  w1h,  EE * DD * HH / 4);
    cvt_half_kernel<<<592, 256>>>(w3,  w3h,  EE * DD * HH / 4);
    cvt_half_kernel<<<592, 256>>>(w2,  w2h,  EE * HH * DD / 4);
    cvt_half_kernel<<<592, 256>>>(ws1, ws1h, DD * HSS / 4);
    cvt_half_kernel<<<592, 256>>>(ws3, ws3h, DD * HSS / 4);
    cvt_half_kernel<<<592, 256>>>(ws2, ws2h, HSS * DD / 4);

    // fused SwiGLU: shared expert (z=0) + routed experts (z=1..8)
    glu_tc<<<dim3(16, 16, 1 + EE), 256, GLU_SMEMB>>>();

    // merged down-proj: all contributions atomically accumulated
    down_tc<<<dim3(8, 16, 1 + EE), 256, DN_SMEMB>>>(out);
}

// round 11
// speedup vs baseline: 4.5433x; 1.0699x over previous
#include <cuda_runtime.h>
#include <cuda_fp16.h>
#include <math.h>
#include <stdint.h>

#define TT  2048
#define DD  1024
#define HH  512
#define HSS 1024
#define EE  8
#define BK  32
#define NST 4

// stage sizes in halves
#define GLU_STGH 8704                  // A 128x32 = 4096, B1 32x72 = 2304, B3 2304
#define GLU_SMEMB (NST * GLU_STGH * 2) // 69632 B
#define DN_STGH  8448                  // A 4096, B 32x136 = 4352
#define DN_SMEMB  (NST * DN_STGH * 2)  // 67584 B

// ---------------- scratch ----------------------------------------------------
__device__ __half g_xh  [(size_t)TT * DD];        // fp16 input
__device__ __half g_hsh [(size_t)TT * HSS];       // fp16 shared hidden
__device__ __half g_hidh[(size_t)EE * TT * HH];   // fp16 routed hidden
__device__ __half g_w1h [(size_t)EE * DD * HH];
__device__ __half g_w3h [(size_t)EE * DD * HH];
__device__ __half g_w2h [(size_t)EE * HH * DD];
__device__ __half g_ws1h[(size_t)DD * HSS];
__device__ __half g_ws3h[(size_t)DD * HSS];
__device__ __half g_ws2h[(size_t)HSS * DD];
__device__ int    g_cnt[EE];
__device__ int    g_tok[EE * TT];
__device__ float  g_wt [EE * TT];

// ---------------- helpers ----------------------------------------------------
__device__ __forceinline__ uint32_t smem_u32(const void* p) {
    uint32_t a;
    asm("{ .reg .u64 t; cvta.to.shared.u64 t, %1; cvt.u32.u64 %0, t; }" : "=r"(a) : "l"(p));
    return a;
}
#define CP16(dst, src) \
    asm volatile("cp.async.cg.shared.global [%0], [%1], 16;" :: "r"((uint32_t)(dst)), "l"(src))
#define CP_COMMIT() asm volatile("cp.async.commit_group;" ::: "memory")
#define CP_WAIT2()  asm volatile("cp.async.wait_group 2;" ::: "memory")

#define LDSM4(r0, r1, r2, r3, addr) \
    asm volatile("ldmatrix.sync.aligned.m8n8.x4.shared.b16 {%0,%1,%2,%3}, [%4];" \
        : "=r"(r0), "=r"(r1), "=r"(r2), "=r"(r3) : "r"(addr))
#define LDSM4T(r0, r1, r2, r3, addr) \
    asm volatile("ldmatrix.sync.aligned.m8n8.x4.trans.shared.b16 {%0,%1,%2,%3}, [%4];" \
        : "=r"(r0), "=r"(r1), "=r"(r2), "=r"(r3) : "r"(addr))

__device__ __forceinline__ void mmah(float* c, const uint32_t* a, uint32_t b0, uint32_t b1) {
    asm volatile(
        "mma.sync.aligned.m16n8k16.row.col.f32.f16.f16.f32 "
        "{%0,%1,%2,%3}, {%4,%5,%6,%7}, {%8,%9}, {%0,%1,%2,%3};"
        : "+f"(c[0]), "+f"(c[1]), "+f"(c[2]), "+f"(c[3])
        : "r"(a[0]), "r"(a[1]), "r"(a[2]), "r"(a[3]), "r"(b0), "r"(b1));
}
__device__ __forceinline__ float silu_f(float v) { return v / (1.f + expf(-v)); }

__device__ __forceinline__ uint32_t pack_h2(float a, float b) {
    __half2 h = __floats2half2_rn(a, b);
    return ((uint32_t)__half_as_ushort(__high2half(h)) << 16)
         | (uint32_t)__half_as_ushort(__low2half(h));
}

// ---------------- init / zero / cvt ------------------------------------------
__global__ void init_kernel() { if (threadIdx.x < EE) g_cnt[threadIdx.x] = 0; }

__global__ void zero_out_kernel(float* __restrict__ out) {
    int i = blockIdx.x * blockDim.x + threadIdx.x;
    ((float4*)out)[i] = make_float4(0.f, 0.f, 0.f, 0.f);
}

// merged fp32 -> fp16 conversion: gridDim.y selects the array; 8 floats/thread/iter
struct CvtArgs {
    const float* src[6];
    __half* dst[6];
    int n8[6];
};
__global__ void cvt_all_kernel(CvtArgs args) {
    const int y = blockIdx.y;
    const float4* s = (const float4*)args.src[y];
    uint4* d = (uint4*)args.dst[y];
    const int n8 = args.n8[y];
    int i = blockIdx.x * blockDim.x + threadIdx.x;
    const int stride = gridDim.x * blockDim.x;
    for (; i < n8; i += stride) {
        float4 v0 = s[i * 2];
        float4 v1 = s[i * 2 + 1];
        uint4 o;
        o.x = pack_h2(v0.x, v0.y);
        o.y = pack_h2(v0.z, v0.w);
        o.z = pack_h2(v1.x, v1.y);
        o.w = pack_h2(v1.z, v1.w);
        d[i] = o;
    }
}

// ---------------- router: scores + top-2 + fp16 x copy -----------------------
__global__ void router_kernel(const float* __restrict__ x, const float* __restrict__ gw) {
    int warp = (blockIdx.x * blockDim.x + threadIdx.x) >> 5;
    int lane = threadIdx.x & 31;
    if (warp >= TT) return;
    const float* xr = x + (size_t)warp * DD;
    __half* xo = g_xh + (size_t)warp * DD;
    float acc[EE];
    #pragma unroll
    for (int e = 0; e < EE; e++) acc[e] = 0.f;
    for (int d = lane; d < DD; d += 32) {
        float xv = xr[d];
        xo[d] = __float2half_rn(xv);
        const float* g = gw + (size_t)d * EE;
        #pragma unroll
        for (int e = 0; e < EE; e++) acc[e] += xv * g[e];
    }
    #pragma unroll
    for (int e = 0; e < EE; e++) {
        #pragma unroll
        for (int o = 16; o > 0; o >>= 1) acc[e] += __shfl_xor_sync(0xFFFFFFFFu, acc[e], o);
    }
    if (lane == 0) {
        float s[EE];
        #pragma unroll
        for (int e = 0; e < EE; e++) s[e] = 1.f / (1.f + expf(-acc[e]));
        int i0 = 0;
        #pragma unroll
        for (int e = 1; e < EE; e++) if (s[e] > s[i0]) i0 = e;
        int i1 = (i0 == 0) ? 1 : 0;
        #pragma unroll
        for (int e = 0; e < EE; e++) { if (e != i0 && s[e] > s[i1]) i1 = e; }
        float sum = s[i0] + s[i1];
        int p0 = atomicAdd(&g_cnt[i0], 1);
        g_tok[i0 * TT + p0] = warp; g_wt[i0 * TT + p0] = s[i0] / sum;
        int p1 = atomicAdd(&g_cnt[i1], 1);
        g_tok[i1 * TT + p1] = warp; g_wt[i1 * TT + p1] = s[i1] / sum;
    }
}

// ---------------- fused SwiGLU GEMM (fp16 mma + ldmatrix) --------------------
// BM=128, BN=64, BK=32, 256 threads, 8 warps = 4(m) x 2(n), warp tile 32x32.
// z==0: shared (A=g_xh, B=g_ws1h/g_ws3h ld HSS, C=g_hsh); z>=1: expert e=z-1
__global__ __launch_bounds__(256, 2)
void glu_tc() {
    extern __shared__ __half smh[];
    const int tid = threadIdx.x;
    const int z = blockIdx.z, e = z - 1;

    int M, ldB, ldC;
    const __half *B1, *B3;
    const int* tok = nullptr;
    __half* C;
    if (z == 0) {
        M = TT; ldB = HSS; ldC = HSS;
        B1 = g_ws1h; B3 = g_ws3h; C = g_hsh;
    } else {
        if (blockIdx.x >= HH / 64) return;
        M = g_cnt[e]; ldB = HH; ldC = HH;
        tok = g_tok + e * TT;
        B1 = g_w1h + (size_t)e * DD * HH;
        B3 = g_w3h + (size_t)e * DD * HH;
        C  = g_hidh + (size_t)e * TT * HH;
    }
    const int m0 = blockIdx.y * 128, n0 = blockIdx.x * 64;
    if (m0 >= M) return;

    const uint32_t sb = smem_u32(smh);

    // producers: A 2 chunks (16B = 8 halves), B1/B3 1 chunk each, per stage
    const __half* aptr[2];
    uint32_t adst[2];
    #pragma unroll
    for (int i = 0; i < 2; i++) {
        int id = tid + i * 256;
        int am = id >> 2, ac = id & 3;                 // row 0..127, chunk 0..3
        int gm = m0 + am;
        int sr = (z == 0) ? gm : ((gm < M) ? tok[gm] : tok[m0]);
        aptr[i] = g_xh + (size_t)sr * DD + ac * 8;
        adst[i] = sb + (uint32_t)(am * 32 + ((ac ^ ((am >> 1) & 3)) * 8)) * 2;
    }
    const int bk = tid >> 3, bch = tid & 7;            // row 0..31, chunk 0..7
    const __half* b1p = B1 + (size_t)bk * ldB + n0 + bch * 8;
    const __half* b3p = B3 + (size_t)bk * ldB + n0 + bch * 8;
    const uint32_t bdst = sb + (uint32_t)(4096 + bk * 72 + bch * 8) * 2;

    const int nit = DD / BK;  // 32

    auto load_stage = [&](int it) {
        if (it < nit) {
            uint32_t so = (uint32_t)(it % NST) * GLU_STGH * 2;
            int k0 = it * BK;
            CP16(adst[0] + so, aptr[0] + k0);
            CP16(adst[1] + so, aptr[1] + k0);
            size_t wko = (size_t)k0 * ldB;
            CP16(bdst + so,            b1p + wko);
            CP16(bdst + so + 2304 * 2, b3p + wko);
        }
        CP_COMMIT();
    };

    const int lane = tid & 31, wid = tid >> 5;
    const int g = lane >> 2, t = lane & 3;
    const int wm = wid >> 1, wn = wid & 1;
    const int hi = lane >> 4;          // 0: k-lo half, 1: k-hi half

    // precompute per-lane ldmatrix byte offsets (within stage)
    uint32_t aoffb[2][2];              // [mf][s]
    #pragma unroll
    for (int mf = 0; mf < 2; mf++) {
        int row = wm * 32 + mf * 16 + (lane & 15);
        #pragma unroll
        for (int s = 0; s < 2; s++) {
            int chunk = (s * 2 + hi) ^ ((row >> 1) & 3);
            aoffb[mf][s] = (uint32_t)(row * 32 + chunk * 8) * 2;
        }
    }
    uint32_t boffb[2][2];              // [nt][s] (B1; B3 = +2304*2)
    #pragma unroll
    for (int nt = 0; nt < 2; nt++) {
        int n_off = wn * 32 + nt * 16 + hi * 8;
        #pragma unroll
        for (int s = 0; s < 2; s++) {
            int kl = s * 16 + ((lane >> 3) & 1) * 8 + (lane & 7);
            boffb[nt][s] = (uint32_t)(4096 + kl * 72 + n_off) * 2;
        }
    }

    float acc1[2][4][4] = {}, acc3[2][4][4] = {};

    for (int p = 0; p < NST - 1; p++) load_stage(p);

    for (int it = 0; it < nit; it++) {
        CP_WAIT2();
        __syncthreads();
        load_stage(it + NST - 1);
        uint32_t stb = sb + (uint32_t)(it % NST) * GLU_STGH * 2;
        #pragma unroll
        for (int s = 0; s < 2; s++) {
            uint32_t a[2][4], b1r[2][4], b3r[2][4];
            #pragma unroll
            for (int mf = 0; mf < 2; mf++)
                LDSM4(a[mf][0], a[mf][1], a[mf][2], a[mf][3], stb + aoffb[mf][s]);
            #pragma unroll
            for (int nt = 0; nt < 2; nt++) {
                LDSM4T(b1r[nt][0], b1r[nt][1], b1r[nt][2], b1r[nt][3], stb + boffb[nt][s]);
                LDSM4T(b3r[nt][0], b3r[nt][1], b3r[nt][2], b3r[nt][3], stb + boffb[nt][s] + 2304 * 2);
            }
            #pragma unroll
            for (int mf = 0; mf < 2; mf++)
                #pragma unroll
                for (int nf = 0; nf < 4; nf++) {
                    mmah(acc1[mf][nf], a[mf], b1r[nf >> 1][(nf & 1) * 2], b1r[nf >> 1][(nf & 1) * 2 + 1]);
                    mmah(acc3[mf][nf], a[mf], b3r[nf >> 1][(nf & 1) * 2], b3r[nf >> 1][(nf & 1) * 2 + 1]);
                }
        }
        __syncthreads();
    }

    // epilogue: C = fp16(silu(acc1) * acc3)
    #pragma unroll
    for (int mf = 0; mf < 2; mf++) {
        #pragma unroll
        for (int nf = 0; nf < 4; nf++) {
            int r0  = m0 + wm * 32 + mf * 16 + g;
            int col = n0 + wn * 32 + nf * 8 + t * 2;
            if (r0 < M) {
                uint32_t v = pack_h2(silu_f(acc1[mf][nf][0]) * acc3[mf][nf][0],
                                     silu_f(acc1[mf][nf][1]) * acc3[mf][nf][1]);
                *(uint32_t*)&C[(size_t)r0 * ldC + col] = v;
            }
            int r1 = r0 + 8;
            if (r1 < M) {
                uint32_t v = pack_h2(silu_f(acc1[mf][nf][2]) * acc3[mf][nf][2],
                                     silu_f(acc1[mf][nf][3]) * acc3[mf][nf][3]);
                *(uint32_t*)&C[(size_t)r1 * ldC + col] = v;
            }
        }
    }
}

// ---------------- merged down-proj GEMM (fp16 mma + ldmatrix) ----------------
// BM=128, BN=128, BK=32, 256 threads, 8 warps = 2(m) x 4(n), warp tile 64x32.
// z==0: shared (A=g_hsh, B=g_ws2h, w=1, token=m); z>=1: routed expert e=z-1
__global__ __launch_bounds__(256, 2)
void down_tc(float* __restrict__ out) {
    extern __shared__ __half smh[];
    const int tid = threadIdx.x;
    const int z = blockIdx.z, e = z - 1;

    int M, Kd;
    const __half *A, *B;
    if (z == 0) { M = TT; Kd = HSS; A = g_hsh; B = g_ws2h; }
    else {
        M = g_cnt[e]; Kd = HH;
        A = g_hidh + (size_t)e * TT * HH;
        B = g_w2h + (size_t)e * HH * DD;
    }
    const int m0 = blockIdx.y * 128, n0 = blockIdx.x * 128;
    if (m0 >= M) return;

    const uint32_t sb = smem_u32(smh);

    const __half* aptr[2];
    uint32_t adst[2];
    #pragma unroll
    for (int i = 0; i < 2; i++) {
        int id = tid + i * 256;
        int am = id >> 2, ac = id & 3;
        int r = m0 + am;
        if (r >= M) r = m0;
        aptr[i] = A + (size_t)r * Kd + ac * 8;
        adst[i] = sb + (uint32_t)(am * 32 + ((ac ^ ((am >> 1) & 3)) * 8)) * 2;
    }
    const __half* bptr[2];
    uint32_t bdst[2];
    #pragma unroll
    for (int i = 0; i < 2; i++) {
        int id = tid + i * 256;
        int k = id >> 4, nch = id & 15;                // row 0..31, chunk 0..15
        bptr[i] = B + (size_t)k * DD + n0 + nch * 8;
        bdst[i] = sb + (uint32_t)(4096 + k * 136 + nch * 8) * 2;
    }
    const int nit = Kd / BK;  // 32 or 16

    auto load_stage = [&](int it) {
        if (it < nit) {
            uint32_t so = (uint32_t)(it % NST) * DN_STGH * 2;
            int k0 = it * BK;
            CP16(adst[0] + so, aptr[0] + k0);
            CP16(adst[1] + so, aptr[1] + k0);
            size_t wko = (size_t)k0 * DD;
            CP16(bdst[0] + so, bptr[0] + wko);
            CP16(bdst[1] + so, bptr[1] + wko);
        }
        CP_COMMIT();
    };

    const int lane = tid & 31, wid = tid >> 5;
    const int g = lane >> 2, t = lane & 3;
    const int wm = wid >> 2, wn = wid & 3;
    const int hi = lane >> 4;

    uint32_t aoffb[4][2];              // [mf][s]
    #pragma unroll
    for (int mf = 0; mf < 4; mf++) {
        int row = wm * 64 + mf * 16 + (lane & 15);
        #pragma unroll
        for (int s = 0; s < 2; s++) {
            int chunk = (s * 2 + hi) ^ ((row >> 1) & 3);
            aoffb[mf][s] = (uint32_t)(row * 32 + chunk * 8) * 2;
        }
    }
    uint32_t boffb[2][2];              // [nt][s]
    #pragma unroll
    for (int nt = 0; nt < 2; nt++) {
        int n_off = wn * 32 + nt * 16 + hi * 8;
        #pragma unroll
        for (int s = 0; s < 2; s++) {
            int kl = s * 16 + ((lane >> 3) & 1) * 8 + (lane & 7);
            boffb[nt][s] = (uint32_t)(4096 + kl * 136 + n_off) * 2;
        }
    }

    float acc[4][4][4] = {};

    for (int p = 0; p < NST - 1; p++) load_stage(p);

    for (int it = 0; it < nit; it++) {
        CP_WAIT2();
        __syncthreads();
        load_stage(it + NST - 1);
        uint32_t stb = sb + (uint32_t)(it % NST) * DN_STGH * 2;
        #pragma unroll
        for (int s = 0; s < 2; s++) {
            uint32_t a[4][4], br[2][4];
            #pragma unroll
            for (int mf = 0; mf < 4; mf++)
                LDSM4(a[mf][0], a[mf][1], a[mf][2], a[mf][3], stb + aoffb[mf][s]);
            #pragma unroll
            for (int nt = 0; nt < 2; nt++)
                LDSM4T(br[nt][0], br[nt][1], br[nt][2], br[nt][3], stb + boffb[nt][s]);
            #pragma unroll
            for (int mf = 0; mf < 4; mf++)
                #pragma unroll
                for (int nf = 0; nf < 4; nf++)
                    mmah(acc[mf][nf], a[mf], br[nf >> 1][(nf & 1) * 2], br[nf >> 1][(nf & 1) * 2 + 1]);
        }
        __syncthreads();
    }

    #pragma unroll
    for (int mf = 0; mf < 4; mf++) {
        #pragma unroll
        for (int nf = 0; nf < 4; nf++) {
            int r0  = m0 + wm * 64 + mf * 16 + g;
            int col = n0 + wn * 32 + nf * 8 + t * 2;
            if (r0 < M) {
                int tk; float w;
                if (z == 0) { tk = r0; w = 1.f; }
                else        { tk = g_tok[e * TT + r0]; w = g_wt[e * TT + r0]; }
                float* orow = out + (size_t)tk * DD + col;
                atomicAdd(orow,     w * acc[mf][nf][0]);
                atomicAdd(orow + 1, w * acc[mf][nf][1]);
            }
            int r1 = r0 + 8;
            if (r1 < M) {
                int tk; float w;
                if (z == 0) { tk = r1; w = 1.f; }
                else        { tk = g_tok[e * TT + r1]; w = g_wt[e * TT + r1]; }
                float* orow = out + (size_t)tk * DD + col;
                atomicAdd(orow,     w * acc[mf][nf][2]);
                atomicAdd(orow + 1, w * acc[mf][nf][3]);
            }
        }
    }
}

// ---------------- launch -----------------------------------------------------
extern "C" void kernel_launch(void* const* d_in, const int* in_sizes, int n_in,
                              void* d_out, int out_size) {
    (void)in_sizes; (void)n_in; (void)out_size;
    const float* x   = (const float*)d_in[0];
    const float* gw  = (const float*)d_in[1];
    const float* w1  = (const float*)d_in[2];
    const float* w3  = (const float*)d_in[3];
    const float* w2  = (const float*)d_in[4];
    const float* ws1 = (const float*)d_in[5];
    const float* ws3 = (const float*)d_in[6];
    const float* ws2 = (const float*)d_in[7];
    float* out = (float*)d_out;

    cudaFuncSetAttribute(glu_tc,  cudaFuncAttributeMaxDynamicSharedMemorySize, GLU_SMEMB);
    cudaFuncSetAttribute(down_tc, cudaFuncAttributeMaxDynamicSharedMemorySize, DN_SMEMB);

    __half *w1h, *w3h, *w2h, *ws1h, *ws3h, *ws2h;
    cudaGetSymbolAddress((void**)&w1h,  g_w1h);
    cudaGetSymbolAddress((void**)&w3h,  g_w3h);
    cudaGetSymbolAddress((void**)&w2h,  g_w2h);
    cudaGetSymbolAddress((void**)&ws1h, g_ws1h);
    cudaGetSymbolAddress((void**)&ws3h, g_ws3h);
    cudaGetSymbolAddress((void**)&ws2h, g_ws2h);

    init_kernel<<<1, 32>>>();
    zero_out_kernel<<<(TT * DD / 4) / 256, 256>>>(out);
    router_kernel<<<TT / 8, 256>>>(x, gw);

    CvtArgs ca;
    ca.src[0] = w1;  ca.dst[0] = w1h;  ca.n8[0] = EE * DD * HH / 8;
    ca.src[1] = w3;  ca.dst[1] = w3h;  ca.n8[1] = EE * DD * HH / 8;
    ca.src[2] = w2;  ca.dst[2] = w2h;  ca.n8[2] = EE * HH * DD / 8;
    ca.src[3] = ws1; ca.dst[3] = ws1h; ca.n8[3] = DD * HSS / 8;
    ca.src[4] = ws3; ca.dst[4] = ws3h; ca.n8[4] = DD * HSS / 8;
    ca.src[5] = ws2; ca.dst[5] = ws2h; ca.n8[5] = HSS * DD / 8;
    cvt_all_kernel<<<dim3(296, 6), 256>>>(ca);

    // fused SwiGLU: shared expert (z=0) + routed experts (z=1..8)
    glu_tc<<<dim3(16, 16, 1 + EE), 256, GLU_SMEMB>>>();

    // merged down-proj: all contributions atomically accumulated
    down_tc<<<dim3(8, 16, 1 + EE), 256, DN_SMEMB>>>(out);
}